// round 2
// baseline (speedup 1.0000x reference)
#include <cuda_runtime.h>
#include <math.h>

#define EPSR 1e-6f
#define NSAMP 256
#define PITCH 204

// ---------------- global scratch (static; no allocation) ----------------
__device__ float g_S[NSAMP * 196 * 204];   // per-sample Gram S = T0^T T0, pitch 204
__device__ float g_P[NSAMP * 196 * 4];     // final projection P (A = T0 @ P)
__device__ float g_gate[NSAMP * 512];      // per-channel sigmoid gate

// ---------------- f32x2 packed FMA helpers (sm_100+) ----------------
__device__ __forceinline__ unsigned long long pk2(float lo, float hi) {
    unsigned long long r;
    asm("mov.b64 %0, {%1, %2};" : "=l"(r) : "f"(lo), "f"(hi));
    return r;
}
__device__ __forceinline__ void upk2(unsigned long long v, float& lo, float& hi) {
    asm("mov.b64 {%0, %1}, %2;" : "=f"(lo), "=f"(hi) : "l"(v));
}
__device__ __forceinline__ void ffma2(unsigned long long& acc, unsigned long long a, unsigned long long b) {
    asm("fma.rn.f32x2 %0, %1, %2, %0;" : "+l"(acc) : "l"(a), "l"(b));
}

// 4x4 inverse, unpivoted Gauss-Jordan (G is SPD: Schur product of Grams + eps*I)
__device__ __forceinline__ void inv4(const float* __restrict__ G, float* __restrict__ out) {
    float a[4][4], v[4][4];
#pragma unroll
    for (int i = 0; i < 4; i++) {
#pragma unroll
        for (int j = 0; j < 4; j++) { a[i][j] = G[i * 4 + j]; v[i][j] = (i == j) ? 1.f : 0.f; }
    }
#pragma unroll
    for (int c = 0; c < 4; c++) {
        float piv = 1.f / a[c][c];
#pragma unroll
        for (int j = 0; j < 4; j++) { a[c][j] *= piv; v[c][j] *= piv; }
#pragma unroll
        for (int r = 0; r < 4; r++) {
            if (r == c) continue;
            float f = a[r][c];
#pragma unroll
            for (int j = 0; j < 4; j++) { a[r][j] -= f * a[c][j]; v[r][j] -= f * v[c][j]; }
        }
    }
#pragma unroll
    for (int i = 0; i < 4; i++)
#pragma unroll
        for (int j = 0; j < 4; j++) out[i * 4 + j] = v[i][j];
}

// =====================================================================
// K1: S = T0^T T0 per sample.  Split-half staging layout:
//   float4-group g (cols 4g..4g+3) of row i stored at slot:
//     g even -> slot g/2        (0..24)
//     g odd  -> slot 26 + g/2   (26..49)
//   q-operand loads (lane-consecutive tq) hit consecutive slots ->
//   4-word lane stride -> conflict-free. p-operand loads are broadcasts.
// =====================================================================
#define K1_S 13312                       // staging: 64 rows * 52 f4 = 3328 f4 = 13312 floats
#define K1_FLOATS (K1_S + 39984)         // + S[196][204] ; 213184 bytes total

__global__ void __launch_bounds__(512, 1)
k1_build_S(const float* __restrict__ x)
{
    extern __shared__ float sm[];
    float4* Tc4 = (float4*)sm;           // [64][52] float4
    float* Ssm = sm + K1_S;

    const int b = blockIdx.x;
    const int t = threadIdx.x;
    const float* xs = x + (size_t)b * 100352;

    // zero never-written pad slots 25,50,51 (read by boundary tiles, results discarded)
    for (int v = t; v < 192; v += 512) {
        int i = v / 3, j = v - 3 * (v / 3);
        int slot = (j == 0) ? 25 : (j == 1 ? 50 : 51);
        Tc4[i * 52 + slot] = make_float4(0.f, 0.f, 0.f, 0.f);
    }

    int tp = 0, tq = 0;
    const bool tact = (t < 325);
    if (tact) {
        int id = t, row = 0;
        while (id >= 25 - row) { id -= 25 - row; ++row; }
        tp = row; tq = row + id;         // tp <= tq, 25*26/2 = 325 tiles of 8x8
    }
    unsigned long long acc[32];
#pragma unroll
    for (int i = 0; i < 32; i++) acc[i] = 0ULL;

    for (int ch = 0; ch < 8; ch++) {
        // stage 64 rows of 196 floats into split-half layout (coalesced-ish gmem reads)
        for (int v = t; v < 3136; v += 512) {
            int i = v / 49, s49 = v - 49 * (v / 49);
            int g, slot;
            if (s49 < 25) { g = s49 * 2; slot = s49; }
            else          { g = (s49 - 25) * 2 + 1; slot = 26 + (s49 - 25); }
            Tc4[i * 52 + slot] = *(const float4*)(xs + ch * 12544 + i * 196 + g * 4);
        }
        __syncthreads();
        if (tact) {
#pragma unroll 2
            for (int i = 0; i < 64; i++) {
                const float4* row = Tc4 + i * 52;
                float4 pA = row[tp];          // cols 8tp..8tp+3  (broadcast across lanes)
                float4 pB = row[26 + tp];     // cols 8tp+4..8tp+7
                float4 qA = row[tq];          // cols 8tq..8tq+3  (lane-consecutive, conflict-free)
                float4 qB = row[26 + tq];     // cols 8tq+4..8tq+7
                unsigned long long qb0 = pk2(qA.x, qA.y);
                unsigned long long qb1 = pk2(qA.z, qA.w);
                unsigned long long qb2 = pk2(qB.x, qB.y);
                unsigned long long qb3 = pk2(qB.z, qB.w);
                float pv[8] = {pA.x, pA.y, pA.z, pA.w, pB.x, pB.y, pB.z, pB.w};
#pragma unroll
                for (int p = 0; p < 8; p++) {
                    unsigned long long pd = pk2(pv[p], pv[p]);
                    ffma2(acc[p * 4 + 0], pd, qb0);
                    ffma2(acc[p * 4 + 1], pd, qb1);
                    ffma2(acc[p * 4 + 2], pd, qb2);
                    ffma2(acc[p * 4 + 3], pd, qb3);
                }
            }
        }
        __syncthreads();
    }

    // scatter tiles (plus symmetric mirror) into smem S
    if (tact) {
#pragma unroll
        for (int p = 0; p < 8; p++) {
            int gp = tp * 8 + p;
            if (gp < 196) {
#pragma unroll
                for (int qp = 0; qp < 4; qp++) {
                    float lo, hi;
                    upk2(acc[p * 4 + qp], lo, hi);
                    int gq = tq * 8 + qp * 2;
                    if (gq < 196) { Ssm[gp * PITCH + gq] = lo; if (tp != tq) Ssm[gq * PITCH + gp] = lo; }
                    if (gq + 1 < 196) { Ssm[gp * PITCH + gq + 1] = hi; if (tp != tq) Ssm[(gq + 1) * PITCH + gp] = hi; }
                }
            }
        }
    }
    __syncthreads();
    // coalesced copy smem S -> global scratch
    {
        float4* gS4 = (float4*)(g_S + (size_t)b * 39984);
        const float4* Ss4 = (const float4*)Ssm;
        for (int v = t; v < 9996; v += 512) gS4[v] = Ss4[v];
    }
}

// =====================================================================
// K2: 20 ALS iterations entirely on smem-resident S.
//   Last iteration computes only P (Q/B/C updates are dead code).
// =====================================================================
#define K2_S 0
#define K2_P 39984
#define K2_Q (K2_P + 784)
#define K2_QP (K2_Q + 784)
#define K2_B (K2_QP + 1568)
#define K2_C (K2_B + 56)
#define K2_BTB (K2_C + 56)
#define K2_CTC (K2_BTB + 16)
#define K2_ATA (K2_CTC + 16)
#define K2_GI (K2_ATA + 16)
#define K2_M (K2_GI + 16)
#define K2_REDA (K2_M + 56)
#define K2_FLOATS (K2_REDA + 224)   // 43600 floats = 174400 B

#define QSTEP(qq)                                                              \
    {                                                                          \
        float4 sv = *(const float4*)(srow + (qq));                             \
        float4 p0 = Pv[(qq) + 0];                                              \
        float4 p1 = Pv[(qq) + 1];                                              \
        float4 p2 = Pv[(qq) + 2];                                              \
        float4 p3 = Pv[(qq) + 3];                                              \
        a0 += sv.x * p0.x + sv.y * p1.x + sv.z * p2.x + sv.w * p3.x;           \
        a1 += sv.x * p0.y + sv.y * p1.y + sv.z * p2.y + sv.w * p3.y;           \
        a2 += sv.x * p0.z + sv.y * p1.z + sv.z * p2.z + sv.w * p3.z;           \
        a3 += sv.x * p0.w + sv.y * p1.w + sv.z * p2.w + sv.w * p3.w;           \
    }

__global__ void __launch_bounds__(512, 1)
k2_als(const float* __restrict__ B0, const float* __restrict__ C0)
{
    extern __shared__ float sm[];
    float* S = sm + K2_S;
    float* P = sm + K2_P;
    float* Q = sm + K2_Q;
    float* Qpart = sm + K2_QP;
    float* sB = sm + K2_B;
    float* sC = sm + K2_C;
    float* sBtB = sm + K2_BTB;
    float* sCtC = sm + K2_CTC;
    float* sAtA = sm + K2_ATA;
    float* sGi = sm + K2_GI;
    float* sM = sm + K2_M;
    float* redA = sm + K2_REDA;

    const int b = blockIdx.x;
    const int t = threadIdx.x;

    // load S (coalesced) and init factors
    {
        const float4* gS4 = (const float4*)(g_S + (size_t)b * 39984);
        float4* Ss4 = (float4*)S;
        for (int v = t; v < 9996; v += 512) Ss4[v] = gS4[v];
    }
    if (t < 56) sB[t] = B0[b * 56 + t];
    else if (t < 112) sC[t - 56] = C0[b * 56 + (t - 56)];
    __syncthreads();

    for (int it = 0; it < 20; it++) {
        // Grams BtB, CtC
        if (t < 32) {
            int which = t >> 4, e = t & 15, a = e >> 2, c2 = e & 3;
            const float* F = which ? sC : sB;
            float s = 0.f;
#pragma unroll
            for (int j = 0; j < 14; j++) s += F[j * 4 + a] * F[j * 4 + c2];
            (which ? sCtC : sBtB)[e] = s;
        }
        __syncthreads();
        if (t == 0) {
            float G[16];
#pragma unroll
            for (int e = 0; e < 16; e++) G[e] = sBtB[e] * sCtC[e] + ((e % 5 == 0) ? EPSR : 0.f);
            inv4(G, sGi);
        }
        __syncthreads();
        // P = KR(B,C) @ Ginv  (A = T0 @ P)
        if (t < 196) {
            int j = t / 14, k = t - j * 14;
            float kr0 = sB[j * 4 + 0] * sC[k * 4 + 0];
            float kr1 = sB[j * 4 + 1] * sC[k * 4 + 1];
            float kr2 = sB[j * 4 + 2] * sC[k * 4 + 2];
            float kr3 = sB[j * 4 + 3] * sC[k * 4 + 3];
#pragma unroll
            for (int r = 0; r < 4; r++)
                P[t * 4 + r] = kr0 * sGi[0 * 4 + r] + kr1 * sGi[1 * 4 + r] +
                               kr2 * sGi[2 * 4 + r] + kr3 * sGi[3 * 4 + r];
        }
        __syncthreads();
        if (it == 19) break;   // final A only needs P; Q/B/C updates are dead

        // Q = S @ P  (= T0^T A).  Compile-time bounds -> fully unrolled.
        if (t < 392) {
            int p = (t < 196) ? t : (t - 196);
            const float* srow = S + p * PITCH;
            const float4* Pv = (const float4*)P;
            float a0 = 0, a1 = 0, a2 = 0, a3 = 0;
            if (t < 196) {
#pragma unroll
                for (int q = 0; q < 96; q += 4) QSTEP(q);
                Qpart[p * 8 + 0] = a0; Qpart[p * 8 + 1] = a1;
                Qpart[p * 8 + 2] = a2; Qpart[p * 8 + 3] = a3;
            } else {
#pragma unroll
                for (int q = 96; q < 196; q += 4) QSTEP(q);
                Qpart[p * 8 + 4] = a0; Qpart[p * 8 + 5] = a1;
                Qpart[p * 8 + 6] = a2; Qpart[p * 8 + 7] = a3;
            }
        }
        __syncthreads();
        if (t < 196) {
#pragma unroll
            for (int r = 0; r < 4; r++)
                Q[t * 4 + r] = Qpart[t * 8 + r] + Qpart[t * 8 + 4 + r];
        }
        __syncthreads();
        // AtA = P^T Q (partials) ; M1[j,r] = sum_k C[k,r] Q[j*14+k, r]
        if (t < 224) {
            int e = t / 14, c = t - (t / 14) * 14;
            int s_ = e >> 2, r = e & 3;
            float v = 0.f;
            int pb = c * 14;
#pragma unroll
            for (int p = 0; p < 14; p++) v += P[(pb + p) * 4 + s_] * Q[(pb + p) * 4 + r];
            redA[e * 14 + c] = v;
        } else if (t >= 256 && t < 312) {
            int e = t - 256; int j = e >> 2, r = e & 3;
            float v = 0.f;
#pragma unroll
            for (int k = 0; k < 14; k++) v += sC[k * 4 + r] * Q[(j * 14 + k) * 4 + r];
            sM[e] = v;
        }
        __syncthreads();
        if (t < 16) {
            float v = 0.f;
#pragma unroll
            for (int c = 0; c < 14; c++) v += redA[t * 14 + c];
            sAtA[t] = v;
        }
        __syncthreads();
        if (t == 0) {
            float G[16];
#pragma unroll
            for (int e = 0; e < 16; e++) G[e] = sAtA[e] * sCtC[e] + ((e % 5 == 0) ? EPSR : 0.f);
            inv4(G, sGi);
        }
        __syncthreads();
        // B = M1 @ Ginv
        if (t < 56) {
            int j = t >> 2, r = t & 3;
            sB[t] = sM[j * 4 + 0] * sGi[0 * 4 + r] + sM[j * 4 + 1] * sGi[1 * 4 + r] +
                    sM[j * 4 + 2] * sGi[2 * 4 + r] + sM[j * 4 + 3] * sGi[3 * 4 + r];
        }
        __syncthreads();
        // BtB (new) ; M2[k,r] = sum_j B_new[j,r] Q[j*14+k, r]
        if (t < 16) {
            int a = t >> 2, c2 = t & 3;
            float s = 0.f;
#pragma unroll
            for (int j = 0; j < 14; j++) s += sB[j * 4 + a] * sB[j * 4 + c2];
            sBtB[t] = s;
        } else if (t >= 64 && t < 120) {
            int e = t - 64; int k = e >> 2, r = e & 3;
            float v = 0.f;
#pragma unroll
            for (int j = 0; j < 14; j++) v += sB[j * 4 + r] * Q[(j * 14 + k) * 4 + r];
            sM[e] = v;
        }
        __syncthreads();
        if (t == 0) {
            float G[16];
#pragma unroll
            for (int e = 0; e < 16; e++) G[e] = sAtA[e] * sBtB[e] + ((e % 5 == 0) ? EPSR : 0.f);
            inv4(G, sGi);
        }
        __syncthreads();
        // C = M2 @ Ginv
        if (t < 56) {
            int k = t >> 2, r = t & 3;
            sC[t] = sM[k * 4 + 0] * sGi[0 * 4 + r] + sM[k * 4 + 1] * sGi[1 * 4 + r] +
                    sM[k * 4 + 2] * sGi[2 * 4 + r] + sM[k * 4 + 3] * sGi[3 * 4 + r];
        }
        __syncthreads();
    }

    // write final P
    if (t < 196) ((float4*)(g_P + (size_t)b * 784))[t] = ((const float4*)P)[t];
}

// =====================================================================
// K3a: A = T0 @ P (smem-staged, coalesced x reads), rank_fc, SE -> gate
// =====================================================================
#define A_P 12800                 // staging: 64 rows * 50 f4 = 3200 f4 = 12800 floats
#define A_Y2 (A_P + 784)
#define A_RED (A_Y2 + 512)
#define A_Z (A_RED + 512)
#define A_W1 (A_Z + 32)
#define A_W2 (A_W1 + 16)
#define A_FLOATS (A_W2 + 4)       // 14660 floats = 58640 B

__global__ void __launch_bounds__(512, 1)
k3a_gate(const float* __restrict__ x, const float* __restrict__ w1,
         const float* __restrict__ w2, const float* __restrict__ fw1,
         const float* __restrict__ fw2)
{
    extern __shared__ float sm[];
    float4* Tc4 = (float4*)sm;             // [64][50] float4, pitch 200 floats
    float* P = sm + A_P;
    float* sy2 = sm + A_Y2;
    float* red = sm + A_RED;
    float* sz = sm + A_Z;
    float* sw1 = sm + A_W1;
    float* sw2 = sm + A_W2;

    const int b = blockIdx.x;
    const int t = threadIdx.x;
    const float* xs = x + (size_t)b * 100352;

    if (t < 196) ((float4*)P)[t] = ((const float4*)(g_P + (size_t)b * 784))[t];
    else if (t >= 256 && t < 272) sw1[t - 256] = w1[t - 256];
    else if (t >= 272 && t < 276) sw2[t - 272] = w2[t - 272];

    const int cl = t >> 3;                 // channel-within-chunk 0..63
    const int s = t & 7;                   // col-slice 0..7 (7 active)
    __syncthreads();

    for (int ch = 0; ch < 8; ch++) {
        for (int v = t; v < 3200; v += 512) {
            int i = v / 50, c4 = v - 50 * (v / 50);
            if (c4 < 49)
                Tc4[i * 50 + c4] = *(const float4*)(xs + ch * 12544 + i * 196 + c4 * 4);
        }
        __syncthreads();
        float a0 = 0, a1 = 0, a2 = 0, a3 = 0;
        if (s < 7) {
            const float* row = sm + cl * 200;
            const float4* Pv = (const float4*)P;
#pragma unroll
            for (int j = 0; j < 7; j++) {
                int q = s * 28 + j * 4;
                float4 xv = *(const float4*)(row + q);
                float4 p0 = Pv[q], p1 = Pv[q + 1], p2 = Pv[q + 2], p3 = Pv[q + 3];
                a0 += xv.x * p0.x + xv.y * p1.x + xv.z * p2.x + xv.w * p3.x;
                a1 += xv.x * p0.y + xv.y * p1.y + xv.z * p2.y + xv.w * p3.y;
                a2 += xv.x * p0.z + xv.y * p1.z + xv.z * p2.z + xv.w * p3.z;
                a3 += xv.x * p0.w + xv.y * p1.w + xv.z * p2.w + xv.w * p3.w;
            }
        }
        // reduce 8-lane slices (all 32 lanes participate)
#pragma unroll
        for (int m = 4; m; m >>= 1) {
            a0 += __shfl_xor_sync(0xffffffffu, a0, m);
            a1 += __shfl_xor_sync(0xffffffffu, a1, m);
            a2 += __shfl_xor_sync(0xffffffffu, a2, m);
            a3 += __shfl_xor_sync(0xffffffffu, a3, m);
        }
        if (s == 0) {
            float y2 = 0.f;
#pragma unroll
            for (int s_ = 0; s_ < 4; s_++) {
                float u = a0 * sw1[s_ * 4 + 0] + a1 * sw1[s_ * 4 + 1] +
                          a2 * sw1[s_ * 4 + 2] + a3 * sw1[s_ * 4 + 3];
                u = fmaxf(u, 0.f);
                y2 += u * sw2[s_];
            }
            sy2[ch * 64 + cl] = y2;
        }
        __syncthreads();
    }

    // z = relu(fw1 @ y2)
    {
        int m = t >> 4, c = t & 15;
        const float* fr = fw1 + m * 512 + c * 32;
        const float* yy = sy2 + c * 32;
        float v = 0.f;
#pragma unroll
        for (int i2 = 0; i2 < 32; i2++) v += fr[i2] * yy[i2];
        red[m * 16 + c] = v;
    }
    __syncthreads();
    if (t < 32) {
        float v = 0.f;
#pragma unroll
        for (int c = 0; c < 16; c++) v += red[t * 16 + c];
        sz[t] = fmaxf(v, 0.f);
    }
    __syncthreads();
    {
        const float* fr = fw2 + t * 32;
        float v = 0.f;
#pragma unroll
        for (int m = 0; m < 32; m++) v += fr[m] * sz[m];
        g_gate[b * 512 + t] = 1.f / (1.f + expf(-v));
    }
}

// =====================================================================
// K3b: out = x * gate[channel]  (pure streaming, bandwidth-sized grid)
// =====================================================================
__global__ void __launch_bounds__(256)
k3b_apply(const float* __restrict__ x, float* __restrict__ out)
{
    const float4* xi = (const float4*)x;
    float4* o = (float4*)out;
    int stride = gridDim.x * 256;
    for (int v = blockIdx.x * 256 + threadIdx.x; v < 6422528; v += stride) {
        int bb = v / 25088;
        int r = v - bb * 25088;
        int c = r / 49;
        float g = __ldg(&g_gate[bb * 512 + c]);
        float4 xv = xi[v];
        o[v] = make_float4(xv.x * g, xv.y * g, xv.z * g, xv.w * g);
    }
}

extern "C" void kernel_launch(void* const* d_in, const int* in_sizes, int n_in,
                              void* d_out, int out_size) {
    const float* x   = (const float*)d_in[0];
    // d_in[1] = A0: unused (A is overwritten before first use in the reference)
    const float* B0  = (const float*)d_in[2];
    const float* C0  = (const float*)d_in[3];
    const float* w1  = (const float*)d_in[4];
    const float* w2  = (const float*)d_in[5];
    const float* fw1 = (const float*)d_in[6];
    const float* fw2 = (const float*)d_in[7];
    float* out = (float*)d_out;

    int b = in_sizes[0] / 100352;   // 256

    size_t sm1 = (size_t)K1_FLOATS * sizeof(float);   // 213184
    size_t sm2 = (size_t)K2_FLOATS * sizeof(float);   // 174400
    size_t sm3 = (size_t)A_FLOATS * sizeof(float);    // 58640
    static int configured = 0;
    if (!configured) {
        cudaFuncSetAttribute(k1_build_S, cudaFuncAttributeMaxDynamicSharedMemorySize, (int)sm1);
        cudaFuncSetAttribute(k2_als,     cudaFuncAttributeMaxDynamicSharedMemorySize, (int)sm2);
        cudaFuncSetAttribute(k3a_gate,   cudaFuncAttributeMaxDynamicSharedMemorySize, (int)sm3);
        configured = 1;
    }

    k1_build_S<<<b, 512, sm1>>>(x);
    k2_als<<<b, 512, sm2>>>(B0, C0);
    k3a_gate<<<b, 512, sm3>>>(x, w1, w2, fw1, fw2);
    k3b_apply<<<2048, 256>>>(x, out);
}

// round 4
// speedup vs baseline: 1.1479x; 1.1479x over previous
#include <cuda_runtime.h>
#include <math.h>

#define EPSR 1e-6f
#define PITCH 204

// ---------------- smem layout (floats) ----------------
// region0 [0,12800): phase1 staging (part) / phase2 small arrays / phase3 staging
// P at 12800 (written by phase2, read by phase3)
#define OFF_P    12800
#define OFF_SY2  13584
#define OFF_S    14336                  // S [196][204] = 39984 -> ends 54320
#define OFF_RED  54320
#define OFF_SZ   54832
#define OFF_SW1  54864
#define OFF_SW2  54880
#define OFF_GATE 54884
#define SMEM_FLOATS (OFF_GATE + 512)    // 55396 floats = 221584 B
// phase2 smalls inside region0:
#define P2_Q    0
#define P2_QP   784
#define P2_B    2352
#define P2_C    2408
#define P2_BTB  2464
#define P2_CTC  2480
#define P2_ATA  2496
#define P2_GI   2512
#define P2_M    2528
#define P2_REDA 2584                    // +224 -> 2808 < 12800 OK

// ---------------- f32x2 packed FMA helpers (sm_100+) ----------------
__device__ __forceinline__ unsigned long long pk2(float lo, float hi) {
    unsigned long long r;
    asm("mov.b64 %0, {%1, %2};" : "=l"(r) : "f"(lo), "f"(hi));
    return r;
}
__device__ __forceinline__ void upk2(unsigned long long v, float& lo, float& hi) {
    asm("mov.b64 {%0, %1}, %2;" : "=f"(lo), "=f"(hi) : "l"(v));
}
__device__ __forceinline__ void ffma2(unsigned long long& acc, unsigned long long a, unsigned long long b) {
    asm("fma.rn.f32x2 %0, %1, %2, %0;" : "+l"(acc) : "l"(a), "l"(b));
}

// Warp-parallel 4x4 SPD inverse via adjugate: lanes 0..15, lane t=(i,j).
// G[e] = ga[e]*gb[e] + eps on diagonal. Writes inv into gi[16].
__device__ __forceinline__ void inv4_warp16(const float* __restrict__ ga,
                                            const float* __restrict__ gb,
                                            float* __restrict__ gi, int t)
{
    float G[16];
#pragma unroll
    for (int e = 0; e < 16; e++)
        G[e] = ga[e] * gb[e] + ((e % 5 == 0) ? EPSR : 0.f);
    int i = t >> 2, j = t & 3;
    int r0 = (i == 0) ? 1 : 0, r1 = (i < 2) ? 2 : 1, r2 = (i < 3) ? 3 : 2;
    int c0 = (j == 0) ? 1 : 0, c1 = (j < 2) ? 2 : 1, c2 = (j < 3) ? 3 : 2;
    float a = G[r0 * 4 + c0], bb = G[r0 * 4 + c1], c = G[r0 * 4 + c2];
    float d = G[r1 * 4 + c0], e  = G[r1 * 4 + c1], f = G[r1 * 4 + c2];
    float g = G[r2 * 4 + c0], h  = G[r2 * 4 + c1], i2 = G[r2 * 4 + c2];
    float det3 = a * (e * i2 - f * h) - bb * (d * i2 - f * g) + c * (d * h - e * g);
    float cof = ((i + j) & 1) ? -det3 : det3;
    const unsigned m16 = 0x0000ffffu;
    float c0v = __shfl_sync(m16, cof, 0);
    float c1v = __shfl_sync(m16, cof, 1);
    float c2v = __shfl_sync(m16, cof, 2);
    float c3v = __shfl_sync(m16, cof, 3);
    float det = G[0] * c0v + G[1] * c1v + G[2] * c2v + G[3] * c3v;
    float cji = __shfl_sync(m16, cof, j * 4 + i);
    gi[t] = cji / det;
}

extern __shared__ float sm[];

__global__ void __launch_bounds__(512, 1)
dese_fused(const float* __restrict__ x, const float* __restrict__ B0,
           const float* __restrict__ C0, const float* __restrict__ w1,
           const float* __restrict__ w2, const float* __restrict__ fw1,
           const float* __restrict__ fw2, float* __restrict__ out)
{
    const int b = blockIdx.x;
    const int t = threadIdx.x;
    const float* xs = x + (size_t)b * 100352;   // T0: [512][196] row-major
    float* S = sm + OFF_S;

    // ================= Phase 1: S = T0^T T0 (split-half staging, FFMA2) =========
    {
        float4* Tc4 = (float4*)sm;              // [64][52] float4 (13312 floats)
        // zero pad slots 25,50,51 once
        for (int v = t; v < 192; v += 512) {
            int i = v / 3, j = v - 3 * (v / 3);
            int slot = (j == 0) ? 25 : (j == 1 ? 50 : 51);
            Tc4[i * 52 + slot] = make_float4(0.f, 0.f, 0.f, 0.f);
        }
        int tp = 0, tq = 0;
        const bool tact = (t < 325);
        if (tact) {
            int id = t, row = 0;
            while (id >= 25 - row) { id -= 25 - row; ++row; }
            tp = row; tq = row + id;            // 8x8 tile (tp<=tq), 325 tiles
        }
        unsigned long long acc[32];
#pragma unroll
        for (int i = 0; i < 32; i++) acc[i] = 0ULL;

        const int w = t >> 5, l = t & 31;       // staging: warp w -> rows 4w..4w+3
        for (int ch = 0; ch < 8; ch++) {
            // stage 64 rows x 196 floats, split-half layout
#pragma unroll
            for (int rr = 0; rr < 4; rr++) {
                int i = w * 4 + rr;
                const float* grow = xs + ch * 12544 + i * 196;
                if (l < 25) Tc4[i * 52 + l] = *(const float4*)(grow + l * 8);            // even g=2l
                if (l < 24) Tc4[i * 52 + 26 + l] = *(const float4*)(grow + l * 8 + 4);   // odd g=2l+1
            }
            __syncthreads();
            if (tact) {
#pragma unroll 2
                for (int i = 0; i < 64; i++) {
                    const float4* row = Tc4 + i * 52;
                    float4 pA = row[tp];        // broadcast
                    float4 pB = row[26 + tp];
                    float4 qA = row[tq];        // lane-consecutive, conflict-free
                    float4 qB = row[26 + tq];
                    unsigned long long qb0 = pk2(qA.x, qA.y);
                    unsigned long long qb1 = pk2(qA.z, qA.w);
                    unsigned long long qb2 = pk2(qB.x, qB.y);
                    unsigned long long qb3 = pk2(qB.z, qB.w);
                    float pv[8] = {pA.x, pA.y, pA.z, pA.w, pB.x, pB.y, pB.z, pB.w};
#pragma unroll
                    for (int p = 0; p < 8; p++) {
                        unsigned long long pd = pk2(pv[p], pv[p]);
                        ffma2(acc[p * 4 + 0], pd, qb0);
                        ffma2(acc[p * 4 + 1], pd, qb1);
                        ffma2(acc[p * 4 + 2], pd, qb2);
                        ffma2(acc[p * 4 + 3], pd, qb3);
                    }
                }
            }
            __syncthreads();
        }
        if (tact) {
#pragma unroll
            for (int p = 0; p < 8; p++) {
                int gp = tp * 8 + p;
                if (gp < 196) {
#pragma unroll
                    for (int qp = 0; qp < 4; qp++) {
                        float lo, hi;
                        upk2(acc[p * 4 + qp], lo, hi);
                        int gq = tq * 8 + qp * 2;
                        if (gq < 196) { S[gp * PITCH + gq] = lo; if (tp != tq) S[gq * PITCH + gp] = lo; }
                        if (gq + 1 < 196) { S[gp * PITCH + gq + 1] = hi; if (tp != tq) S[(gq + 1) * PITCH + gp] = hi; }
                    }
                }
            }
        }
    }

    // ================= Phase 2: 20 ALS iterations on smem S =================
    {
        float* P = sm + OFF_P;
        float* Q = sm + P2_Q;
        float* Qpart = sm + P2_QP;
        float* sB = sm + P2_B;
        float* sC = sm + P2_C;
        float* sBtB = sm + P2_BTB;
        float* sCtC = sm + P2_CTC;
        float* sAtA = sm + P2_ATA;
        float* sGi = sm + P2_GI;
        float* sM = sm + P2_M;
        float* redA = sm + P2_REDA;

        if (t >= 400 && t < 456) sB[t - 400] = B0[b * 56 + (t - 400)];
        else if (t >= 456 && t < 512) sC[t - 456] = C0[b * 56 + (t - 456)];
        __syncthreads();

        for (int it = 0; it < 20; it++) {
            // Grams BtB, CtC + inverse — all inside warp 0
            if (t < 32) {
                int which = t >> 4, e = t & 15, a = e >> 2, c2 = e & 3;
                const float* F = which ? sC : sB;
                float s = 0.f;
#pragma unroll
                for (int j = 0; j < 14; j++) s += F[j * 4 + a] * F[j * 4 + c2];
                (which ? sCtC : sBtB)[e] = s;
                __syncwarp();
                if (t < 16) inv4_warp16(sBtB, sCtC, sGi, t);
            }
            __syncthreads();
            // P = KR(B,C) @ Ginv  (A = T0 @ P)
            if (t < 196) {
                int j = t / 14, k = t - j * 14;
                float kr0 = sB[j * 4 + 0] * sC[k * 4 + 0];
                float kr1 = sB[j * 4 + 1] * sC[k * 4 + 1];
                float kr2 = sB[j * 4 + 2] * sC[k * 4 + 2];
                float kr3 = sB[j * 4 + 3] * sC[k * 4 + 3];
#pragma unroll
                for (int r = 0; r < 4; r++)
                    P[t * 4 + r] = kr0 * sGi[0 * 4 + r] + kr1 * sGi[1 * 4 + r] +
                                   kr2 * sGi[2 * 4 + r] + kr3 * sGi[3 * 4 + r];
            }
            __syncthreads();
            if (it == 19) break;            // final A needs only P

            // Q = S @ P  (= T0^T A); 392 threads, partial unroll
            if (t < 392) {
                int p = (t < 196) ? t : (t - 196);
                const float* srow = S + p * PITCH;
                const float4* Pv = (const float4*)P;
                float a0 = 0, a1 = 0, a2 = 0, a3 = 0;
                int q0 = (t < 196) ? 0 : 96;
                int q1 = (t < 196) ? 96 : 196;
#pragma unroll 4
                for (int q = q0; q < q1; q += 4) {
                    float4 sv = *(const float4*)(srow + q);
                    float4 p0 = Pv[q + 0];
                    float4 p1 = Pv[q + 1];
                    float4 p2 = Pv[q + 2];
                    float4 p3 = Pv[q + 3];
                    a0 += sv.x * p0.x + sv.y * p1.x + sv.z * p2.x + sv.w * p3.x;
                    a1 += sv.x * p0.y + sv.y * p1.y + sv.z * p2.y + sv.w * p3.y;
                    a2 += sv.x * p0.z + sv.y * p1.z + sv.z * p2.z + sv.w * p3.z;
                    a3 += sv.x * p0.w + sv.y * p1.w + sv.z * p2.w + sv.w * p3.w;
                }
                int h = (t < 196) ? 0 : 1;
                Qpart[p * 8 + h * 4 + 0] = a0;
                Qpart[p * 8 + h * 4 + 1] = a1;
                Qpart[p * 8 + h * 4 + 2] = a2;
                Qpart[p * 8 + h * 4 + 3] = a3;
            }
            __syncthreads();
            if (t < 196) {
#pragma unroll
                for (int r = 0; r < 4; r++)
                    Q[t * 4 + r] = Qpart[t * 8 + r] + Qpart[t * 8 + 4 + r];
            }
            __syncthreads();
            // AtA partials (224 thr) ; M1 (56 thr)
            if (t < 224) {
                int e = t / 14, c = t - (t / 14) * 14;
                int s_ = e >> 2, r = e & 3;
                float v = 0.f;
                int pb = c * 14;
#pragma unroll
                for (int p = 0; p < 14; p++) v += P[(pb + p) * 4 + s_] * Q[(pb + p) * 4 + r];
                redA[e * 14 + c] = v;
            } else if (t >= 256 && t < 312) {
                int e = t - 256; int j = e >> 2, r = e & 3;
                float v = 0.f;
#pragma unroll
                for (int k = 0; k < 14; k++) v += sC[k * 4 + r] * Q[(j * 14 + k) * 4 + r];
                sM[e] = v;
            }
            __syncthreads();
            // reduce AtA + inverse in warp 0
            if (t < 32) {
                if (t < 16) {
                    float v = 0.f;
#pragma unroll
                    for (int c = 0; c < 14; c++) v += redA[t * 14 + c];
                    sAtA[t] = v;
                }
                __syncwarp();
                if (t < 16) inv4_warp16(sAtA, sCtC, sGi, t);
            }
            __syncthreads();
            // B = M1 @ Ginv
            if (t < 56) {
                int j = t >> 2, r = t & 3;
                sB[t] = sM[j * 4 + 0] * sGi[0 * 4 + r] + sM[j * 4 + 1] * sGi[1 * 4 + r] +
                        sM[j * 4 + 2] * sGi[2 * 4 + r] + sM[j * 4 + 3] * sGi[3 * 4 + r];
            }
            __syncthreads();
            // BtB (warp0) + inverse ; M2 (warps 2-3)
            if (t < 32) {
                if (t < 16) {
                    int a = t >> 2, c2 = t & 3;
                    float s = 0.f;
#pragma unroll
                    for (int j = 0; j < 14; j++) s += sB[j * 4 + a] * sB[j * 4 + c2];
                    sBtB[t] = s;
                }
                __syncwarp();
                if (t < 16) inv4_warp16(sAtA, sBtB, sGi, t);
            } else if (t >= 64 && t < 120) {
                int e = t - 64; int k = e >> 2, r = e & 3;
                float v = 0.f;
#pragma unroll
                for (int j = 0; j < 14; j++) v += sB[j * 4 + r] * Q[(j * 14 + k) * 4 + r];
                sM[e] = v;
            }
            __syncthreads();
            // C = M2 @ Ginv
            if (t < 56) {
                int k = t >> 2, r = t & 3;
                sC[t] = sM[k * 4 + 0] * sGi[0 * 4 + r] + sM[k * 4 + 1] * sGi[1 * 4 + r] +
                        sM[k * 4 + 2] * sGi[2 * 4 + r] + sM[k * 4 + 3] * sGi[3 * 4 + r];
            }
            __syncthreads();
        }
    }

    // ================= Phase 3: A = T0@P, rank_fc, SE gate, apply =================
    {
        float4* Tc4 = (float4*)sm;              // [64][50] float4 = 12800 floats
        float* P = sm + OFF_P;
        float* sy2 = sm + OFF_SY2;
        float* red = sm + OFF_RED;
        float* sz = sm + OFF_SZ;
        float* sw1 = sm + OFF_SW1;
        float* sw2 = sm + OFF_SW2;
        float* sg = sm + OFF_GATE;

        if (t >= 448 && t < 464) sw1[t - 448] = w1[t - 448];
        else if (t >= 464 && t < 468) sw2[t - 464] = w2[t - 464];

        const int cl = t >> 3;                  // channel-within-chunk 0..63
        const int s = t & 7;                    // col-slice (7 active)
        __syncthreads();

        for (int ch = 0; ch < 8; ch++) {
            for (int v = t; v < 3200; v += 512) {
                int i = v / 50, c4 = v - 50 * (v / 50);
                if (c4 < 49)
                    Tc4[i * 50 + c4] = *(const float4*)(xs + ch * 12544 + i * 196 + c4 * 4);
            }
            __syncthreads();
            float a0 = 0, a1 = 0, a2 = 0, a3 = 0;
            if (s < 7) {
                const float* row = sm + cl * 200;
                const float4* Pv = (const float4*)P;
#pragma unroll
                for (int j = 0; j < 7; j++) {
                    int q = s * 28 + j * 4;
                    float4 xv = *(const float4*)(row + q);
                    float4 p0 = Pv[q], p1 = Pv[q + 1], p2 = Pv[q + 2], p3 = Pv[q + 3];
                    a0 += xv.x * p0.x + xv.y * p1.x + xv.z * p2.x + xv.w * p3.x;
                    a1 += xv.x * p0.y + xv.y * p1.y + xv.z * p2.y + xv.w * p3.y;
                    a2 += xv.x * p0.z + xv.y * p1.z + xv.z * p2.z + xv.w * p3.z;
                    a3 += xv.x * p0.w + xv.y * p1.w + xv.z * p2.w + xv.w * p3.w;
                }
            }
#pragma unroll
            for (int m = 4; m; m >>= 1) {
                a0 += __shfl_xor_sync(0xffffffffu, a0, m);
                a1 += __shfl_xor_sync(0xffffffffu, a1, m);
                a2 += __shfl_xor_sync(0xffffffffu, a2, m);
                a3 += __shfl_xor_sync(0xffffffffu, a3, m);
            }
            if (s == 0) {
                float y2 = 0.f;
#pragma unroll
                for (int s_ = 0; s_ < 4; s_++) {
                    float u = a0 * sw1[s_ * 4 + 0] + a1 * sw1[s_ * 4 + 1] +
                              a2 * sw1[s_ * 4 + 2] + a3 * sw1[s_ * 4 + 3];
                    u = fmaxf(u, 0.f);
                    y2 += u * sw2[s_];
                }
                sy2[ch * 64 + cl] = y2;
            }
            __syncthreads();
        }
        // z = relu(fw1 @ y2)
        {
            int m = t >> 4, c = t & 15;
            const float* fr = fw1 + m * 512 + c * 32;
            const float* yy = sy2 + c * 32;
            float v = 0.f;
#pragma unroll
            for (int i2 = 0; i2 < 32; i2++) v += fr[i2] * yy[i2];
            red[m * 16 + c] = v;
        }
        __syncthreads();
        if (t < 32) {
            float v = 0.f;
#pragma unroll
            for (int c = 0; c < 16; c++) v += red[t * 16 + c];
            sz[t] = fmaxf(v, 0.f);
        }
        __syncthreads();
        {
            const float* fr = fw2 + t * 32;
            float v = 0.f;
#pragma unroll
            for (int m = 0; m < 32; m++) v += fr[m] * sz[m];
            sg[t] = 1.f / (1.f + expf(-v));
        }
        __syncthreads();
        // apply gate: out = x * g[channel]; warp w owns channels w, w+16, ...
        {
            const float4* xin4 = (const float4*)xs;
            float4* out4 = (float4*)(out + (size_t)b * 100352);
            int w = t >> 5, l = t & 31;
            for (int c = w; c < 512; c += 16) {
                float g = sg[c];
                const float4* xr = xin4 + c * 49;
                float4* orow = out4 + c * 49;
                float4 xv = xr[l];
                if (l < 17) {
                    float4 xv2 = xr[l + 32];
                    orow[l + 32] = make_float4(xv2.x * g, xv2.y * g, xv2.z * g, xv2.w * g);
                }
                orow[l] = make_float4(xv.x * g, xv.y * g, xv.z * g, xv.w * g);
            }
        }
    }
}

extern "C" void kernel_launch(void* const* d_in, const int* in_sizes, int n_in,
                              void* d_out, int out_size) {
    const float* x   = (const float*)d_in[0];
    // d_in[1] = A0: unused (A is overwritten before first use in the reference)
    const float* B0  = (const float*)d_in[2];
    const float* C0  = (const float*)d_in[3];
    const float* w1  = (const float*)d_in[4];
    const float* w2  = (const float*)d_in[5];
    const float* fw1 = (const float*)d_in[6];
    const float* fw2 = (const float*)d_in[7];
    float* out = (float*)d_out;

    int b = in_sizes[0] / 100352;                        // 256
    size_t smem = (size_t)SMEM_FLOATS * sizeof(float);   // 221584 B
    static int configured = 0;
    if (!configured) {
        cudaFuncSetAttribute(dese_fused, cudaFuncAttributeMaxDynamicSharedMemorySize, (int)smem);
        configured = 1;
    }
    dese_fused<<<b, 512, smem>>>(x, B0, C0, w1, w2, fw1, fw2, out);
}